// round 3
// baseline (speedup 1.0000x reference)
#include <cuda_runtime.h>
#include <cstdint>

// Problem constants (fixed by the reference)
#define BB    8
#define SS    2048
#define DD    256
#define ADIM  64

#define BM      64          // query tile
#define BN      64          // key tile
#define THREADS 256
#define QPAD    260         // floats per smem row (D + 4) -> bank-stride 4
#define PPAD    68          // P tile row stride

// smem: Q tile (BM x QPAD) | K tile (BN x QPAD, reused as A_det) | P tile (BM x PPAD)
#define SMEM_FLOATS (BM*QPAD + BN*QPAD + BM*PPAD)
#define SMEM_BYTES  (SMEM_FLOATS * 4)

__global__ __launch_bounds__(THREADS, 1)
void vs_attn_vae_kernel(const float* __restrict__ x,
                        const float* __restrict__ Wm,
                        const float* __restrict__ bm,
                        const float* __restrict__ Wl,
                        const float* __restrict__ bl,
                        const float* __restrict__ eps,
                        float* __restrict__ out)
{
    extern __shared__ float smem[];
    float* Qs = smem;                       // [BM][QPAD]
    float* Ks = smem + BM * QPAD;           // [BN][QPAD]  (phase2: A_det)
    float* Ps = smem + 2 * BM * QPAD;       // [BM][PPAD]

    const int b  = blockIdx.y;
    const int qt = blockIdx.x;
    const int t  = threadIdx.x;
    const int ty = t >> 4;                  // 0..15
    const int tx = t & 15;                  // 0..15

    const float* xb = x + (size_t)b * SS * DD;
    const float* xq = xb + (size_t)qt * BM * DD;

    // ---- load Q tile (64 x 256) into padded smem ----
    {
        const float4* src = (const float4*)xq;
        #pragma unroll
        for (int i = t; i < BM * DD / 4; i += THREADS) {
            int r  = i >> 6;                // 64 float4 per row
            int c4 = i & 63;
            ((float4*)(Qs + r * QPAD))[c4] = src[i];
        }
    }

    float acc[4][16];                       // O accumulator: rows ty*4+i, cols tx*16+jj
    #pragma unroll
    for (int i = 0; i < 4; i++)
        #pragma unroll
        for (int j = 0; j < 16; j++) acc[i][j] = 0.0f;

    float rs[4] = {0.0f, 0.0f, 0.0f, 0.0f}; // partial row sums (this thread's 4 cols/tile)

    const float scale = 0.0625f;            // 1/sqrt(256)

    for (int kt = 0; kt < SS / BN; kt++) {
        __syncthreads();                    // prior PV done with Ks/Ps
        // ---- load K tile (also V) ----
        {
            const float4* src = (const float4*)(xb + (size_t)kt * BN * DD);
            #pragma unroll
            for (int i = t; i < BN * DD / 4; i += THREADS) {
                int r  = i >> 6;
                int c4 = i & 63;
                ((float4*)(Ks + r * QPAD))[c4] = src[i];
            }
        }
        __syncthreads();

        // ---- S = Q K^T : 4x4 per thread, float4 over k ----
        float s[4][4];
        #pragma unroll
        for (int i = 0; i < 4; i++)
            #pragma unroll
            for (int j = 0; j < 4; j++) s[i][j] = 0.0f;

        #pragma unroll 4
        for (int kk = 0; kk < DD / 4; kk++) {
            float4 qv[4], kv[4];
            #pragma unroll
            for (int i = 0; i < 4; i++)
                qv[i] = ((const float4*)(Qs + (ty * 4 + i) * QPAD))[kk];
            #pragma unroll
            for (int j = 0; j < 4; j++)
                kv[j] = ((const float4*)(Ks + (tx * 4 + j) * QPAD))[kk];
            #pragma unroll
            for (int i = 0; i < 4; i++)
                #pragma unroll
                for (int j = 0; j < 4; j++)
                    s[i][j] += qv[i].x * kv[j].x + qv[i].y * kv[j].y
                             + qv[i].z * kv[j].z + qv[i].w * kv[j].w;
        }

        // ---- P = exp(S*scale); accumulate row sums; stage P in smem ----
        #pragma unroll
        for (int i = 0; i < 4; i++) {
            #pragma unroll
            for (int j = 0; j < 4; j++) {
                float p = __expf(s[i][j] * scale);
                rs[i] += p;
                Ps[(ty * 4 + i) * PPAD + tx * 4 + j] = p;
            }
        }
        __syncthreads();

        // ---- acc += P @ V (V = K tile) ----
        #pragma unroll 4
        for (int n = 0; n < BN; n++) {
            float p0 = Ps[(ty * 4 + 0) * PPAD + n];
            float p1 = Ps[(ty * 4 + 1) * PPAD + n];
            float p2 = Ps[(ty * 4 + 2) * PPAD + n];
            float p3 = Ps[(ty * 4 + 3) * PPAD + n];
            const float4* kr = (const float4*)(Ks + n * QPAD) + tx * 4;
            float4 k0 = kr[0], k1 = kr[1], k2 = kr[2], k3 = kr[3];
            #define PV_UPD(pi, ii)                                             \
                acc[ii][0]  += pi * k0.x; acc[ii][1]  += pi * k0.y;            \
                acc[ii][2]  += pi * k0.z; acc[ii][3]  += pi * k0.w;            \
                acc[ii][4]  += pi * k1.x; acc[ii][5]  += pi * k1.y;            \
                acc[ii][6]  += pi * k1.z; acc[ii][7]  += pi * k1.w;            \
                acc[ii][8]  += pi * k2.x; acc[ii][9]  += pi * k2.y;            \
                acc[ii][10] += pi * k2.z; acc[ii][11] += pi * k2.w;            \
                acc[ii][12] += pi * k3.x; acc[ii][13] += pi * k3.y;            \
                acc[ii][14] += pi * k3.z; acc[ii][15] += pi * k3.w;
            PV_UPD(p0, 0) PV_UPD(p1, 1) PV_UPD(p2, 2) PV_UPD(p3, 3)
            #undef PV_UPD
        }
    }

    __syncthreads();    // last PV done reading Ks before we overwrite with A_det

    // ---- finalize row sums: reduce across the 16 tx lanes (same half-warp) ----
    #pragma unroll
    for (int m = 1; m < 16; m <<= 1) {
        #pragma unroll
        for (int i = 0; i < 4; i++)
            rs[i] += __shfl_xor_sync(0xffffffffu, rs[i], m);
    }

    // ---- normalize and stage A_det into Ks buffer ----
    #pragma unroll
    for (int i = 0; i < 4; i++) {
        float inv = 1.0f / rs[i];
        #pragma unroll
        for (int jj = 0; jj < 16; jj++)
            Ks[(ty * 4 + i) * QPAD + tx * 16 + jj] = acc[i][jj] * inv;
    }
    __syncthreads();

    // ---- projections: A_mean / A_logvar (4 rows x 4 cols per thread) ----
    float am[4][4], al[4][4];
    #pragma unroll
    for (int i = 0; i < 4; i++)
        #pragma unroll
        for (int j = 0; j < 4; j++) { am[i][j] = 0.0f; al[i][j] = 0.0f; }

    const float4* wm4 = (const float4*)Wm;   // [DD][ADIM] -> row k has 16 float4
    const float4* wl4 = (const float4*)Wl;

    #pragma unroll 8
    for (int k = 0; k < DD; k++) {
        float a0 = Ks[(ty * 4 + 0) * QPAD + k];
        float a1 = Ks[(ty * 4 + 1) * QPAD + k];
        float a2 = Ks[(ty * 4 + 2) * QPAD + k];
        float a3 = Ks[(ty * 4 + 3) * QPAD + k];
        float4 m4 = wm4[k * 16 + tx];
        float4 l4 = wl4[k * 16 + tx];
        #define PR_UPD(ai, ii)                                                 \
            am[ii][0] += ai * m4.x; am[ii][1] += ai * m4.y;                    \
            am[ii][2] += ai * m4.z; am[ii][3] += ai * m4.w;                    \
            al[ii][0] += ai * l4.x; al[ii][1] += ai * l4.y;                    \
            al[ii][2] += ai * l4.z; al[ii][3] += ai * l4.w;
        PR_UPD(a0, 0) PR_UPD(a1, 1) PR_UPD(a2, 2) PR_UPD(a3, 3)
        #undef PR_UPD
    }

    // ---- epilogue: biases, reparameterize, store 3 outputs ----
    const size_t BSA = (size_t)BB * SS * ADIM;      // 1048576
    float4 bm4 = ((const float4*)bm)[tx];
    float4 bl4 = ((const float4*)bl)[tx];

    #pragma unroll
    for (int i = 0; i < 4; i++) {
        int row = qt * BM + ty * 4 + i;
        size_t base = (((size_t)b * SS + row) * ADIM) + tx * 4;
        float4 e4 = *((const float4*)(eps + base));

        float4 mo, lo, ao;
        mo.x = am[i][0] + bm4.x;  mo.y = am[i][1] + bm4.y;
        mo.z = am[i][2] + bm4.z;  mo.w = am[i][3] + bm4.w;
        lo.x = al[i][0] + bl4.x;  lo.y = al[i][1] + bl4.y;
        lo.z = al[i][2] + bl4.z;  lo.w = al[i][3] + bl4.w;
        ao.x = mo.x + __expf(0.5f * lo.x) * e4.x;
        ao.y = mo.y + __expf(0.5f * lo.y) * e4.y;
        ao.z = mo.z + __expf(0.5f * lo.z) * e4.z;
        ao.w = mo.w + __expf(0.5f * lo.w) * e4.w;

        *((float4*)(out + base))            = mo;
        *((float4*)(out + BSA + base))      = lo;
        *((float4*)(out + 2 * BSA + base))  = ao;
    }
}

extern "C" void kernel_launch(void* const* d_in, const int* in_sizes, int n_in,
                              void* d_out, int out_size)
{
    const float* x   = (const float*)d_in[0];
    const float* Wm  = (const float*)d_in[1];
    const float* bm  = (const float*)d_in[2];
    const float* Wl  = (const float*)d_in[3];
    const float* bl  = (const float*)d_in[4];
    const float* eps = (const float*)d_in[5];
    float* out = (float*)d_out;

    cudaFuncSetAttribute(vs_attn_vae_kernel,
                         cudaFuncAttributeMaxDynamicSharedMemorySize, SMEM_BYTES);

    dim3 grid(SS / BM, BB);
    vs_attn_vae_kernel<<<grid, THREADS, SMEM_BYTES>>>(x, Wm, bm, Wl, bl, eps, out);
}

// round 5
// speedup vs baseline: 2.1365x; 2.1365x over previous
#include <cuda_runtime.h>
#include <cstdint>

// Problem constants
#define BB    8
#define SS    2048
#define DD    256
#define ADIM  64

#define BM      64
#define BN      64
#define THREADS 256
#define QPAD    260         // floats/row; 260 mod 32 = 4 (bank stagger), 16B-aligned rows
#define PPAD    68          // 68 mod 32 = 4
#define NTILES  (SS / BN)

// smem: Q (BM x QPAD) | K0 (BN x QPAD) | K1 (BN x QPAD) | P (BM x PPAD)
#define SMEM_FLOATS (3 * BM * QPAD + BM * PPAD)
#define SMEM_BYTES  (SMEM_FLOATS * 4)

__device__ __forceinline__ void cp_async16(uint32_t saddr, const void* gptr) {
    asm volatile("cp.async.cg.shared.global [%0], [%1], 16;\n" :: "r"(saddr), "l"(gptr));
}
__device__ __forceinline__ void cp_commit() { asm volatile("cp.async.commit_group;\n" ::: "memory"); }
__device__ __forceinline__ void cp_wait0()  { asm volatile("cp.async.wait_group 0;\n" ::: "memory"); }

__global__ __launch_bounds__(THREADS, 1)
void vs_attn_vae_kernel(const float* __restrict__ x,
                        const float* __restrict__ Wm,
                        const float* __restrict__ bm,
                        const float* __restrict__ Wl,
                        const float* __restrict__ bl,
                        const float* __restrict__ eps,
                        float* __restrict__ out)
{
    extern __shared__ float smem[];
    float* Qs = smem;                               // [BM][QPAD]; reused as A_det
    float* K0 = smem + BM * QPAD;
    float* K1 = smem + 2 * BM * QPAD;
    float* Ps = smem + 3 * BM * QPAD;               // [BM][PPAD]

    const int b  = blockIdx.y;
    const int qt = blockIdx.x;
    const int t  = threadIdx.x;
    const int ty = t >> 4;                          // 0..15
    const int tx = t & 15;                          // 0..15

    const float* xb = x + (size_t)b * SS * DD;

    // --- prefetch helpers: 16 x 16B per thread per 64x256 tile ---
    auto issue_tile = [&](const float* src, float* dst) {
        #pragma unroll
        for (int k = 0; k < 16; k++) {
            int i  = t + k * THREADS;               // 0..4095 float4 slots
            int r  = i >> 6;
            int c4 = i & 63;
            uint32_t saddr = (uint32_t)__cvta_generic_to_shared(dst + r * QPAD + c4 * 4);
            cp_async16(saddr, src + i * 4);
        }
        cp_commit();
    };

    // prefetch K tile 0 and Q tile (one group; wait once)
    issue_tile(xb, K0);
    issue_tile(xb + (size_t)qt * BM * DD, Qs);
    cp_wait0();
    __syncthreads();

    float acc[4][16];   // rows ty*4+i ; cols 4*tx + 64*g + c  -> acc[i][g*4+c]
    #pragma unroll
    for (int i = 0; i < 4; i++)
        #pragma unroll
        for (int j = 0; j < 16; j++) acc[i][j] = 0.0f;

    float rs[4] = {0.f, 0.f, 0.f, 0.f};
    const float scale = 0.0625f;

    for (int kt = 0; kt < NTILES; kt++) {
        float* cur = (kt & 1) ? K1 : K0;
        if (kt + 1 < NTILES)
            issue_tile(xb + (size_t)(kt + 1) * BN * DD, (kt & 1) ? K0 : K1);

        // ---- S = Q K^T : rows ty*4+i, key rows tx+16j (conflict-free) ----
        float s[4][4];
        #pragma unroll
        for (int i = 0; i < 4; i++)
            #pragma unroll
            for (int j = 0; j < 4; j++) s[i][j] = 0.0f;

        #pragma unroll 2
        for (int kk = 0; kk < DD / 4; kk++) {
            float4 qv[4], kv[4];
            #pragma unroll
            for (int i = 0; i < 4; i++)
                qv[i] = ((const float4*)(Qs + (ty * 4 + i) * QPAD))[kk];
            #pragma unroll
            for (int j = 0; j < 4; j++)
                kv[j] = ((const float4*)(cur + (tx + 16 * j) * QPAD))[kk];
            #pragma unroll
            for (int i = 0; i < 4; i++)
                #pragma unroll
                for (int j = 0; j < 4; j++)
                    s[i][j] += qv[i].x * kv[j].x + qv[i].y * kv[j].y
                             + qv[i].z * kv[j].z + qv[i].w * kv[j].w;
        }

        // ---- P = exp(S/16); row-sum partials; stage P (conflict-free) ----
        #pragma unroll
        for (int i = 0; i < 4; i++) {
            #pragma unroll
            for (int j = 0; j < 4; j++) {
                float p = __expf(s[i][j] * scale);
                rs[i] += p;
                Ps[(ty * 4 + i) * PPAD + tx + 16 * j] = p;
            }
        }
        __syncthreads();

        // ---- acc += P @ V : V cols 4tx+64g (conflict-free float4) ----
        #pragma unroll 2
        for (int n = 0; n < BN; n++) {
            float p0 = Ps[(ty * 4 + 0) * PPAD + n];
            float p1 = Ps[(ty * 4 + 1) * PPAD + n];
            float p2 = Ps[(ty * 4 + 2) * PPAD + n];
            float p3 = Ps[(ty * 4 + 3) * PPAD + n];
            const float4* vr = (const float4*)(cur + n * QPAD);
            float4 v0 = vr[tx +  0];
            float4 v1 = vr[tx + 16];
            float4 v2 = vr[tx + 32];
            float4 v3 = vr[tx + 48];
            #define PV_UPD(pi, ii)                                             \
                acc[ii][0]  += pi * v0.x; acc[ii][1]  += pi * v0.y;            \
                acc[ii][2]  += pi * v0.z; acc[ii][3]  += pi * v0.w;            \
                acc[ii][4]  += pi * v1.x; acc[ii][5]  += pi * v1.y;            \
                acc[ii][6]  += pi * v1.z; acc[ii][7]  += pi * v1.w;            \
                acc[ii][8]  += pi * v2.x; acc[ii][9]  += pi * v2.y;            \
                acc[ii][10] += pi * v2.z; acc[ii][11] += pi * v2.w;            \
                acc[ii][12] += pi * v3.x; acc[ii][13] += pi * v3.y;            \
                acc[ii][14] += pi * v3.z; acc[ii][15] += pi * v3.w;
            PV_UPD(p0, 0) PV_UPD(p1, 1) PV_UPD(p2, 2) PV_UPD(p3, 3)
            #undef PV_UPD
        }

        if (kt + 1 < NTILES) cp_wait0();
        __syncthreads();    // PV done with cur/Ps; next K buffer fully landed
    }

    // ---- finalize row sums: thread's cols tx+16j; reduce across 16 tx lanes ----
    #pragma unroll
    for (int m = 1; m < 16; m <<= 1) {
        #pragma unroll
        for (int i = 0; i < 4; i++)
            rs[i] += __shfl_xor_sync(0xffffffffu, rs[i], m);
    }

    // ---- normalize; stage A_det into Qs (conflict-free float4 stores) ----
    #pragma unroll
    for (int i = 0; i < 4; i++) {
        float inv = 1.0f / rs[i];
        #pragma unroll
        for (int g = 0; g < 4; g++) {
            float4 v;
            v.x = acc[i][g * 4 + 0] * inv;
            v.y = acc[i][g * 4 + 1] * inv;
            v.z = acc[i][g * 4 + 2] * inv;
            v.w = acc[i][g * 4 + 3] * inv;
            ((float4*)(Qs + (ty * 4 + i) * QPAD))[tx + 16 * g] = v;
        }
    }
    __syncthreads();

    // ---- projections: A_mean / A_logvar ----
    float am[4][4], al[4][4];
    #pragma unroll
    for (int i = 0; i < 4; i++)
        #pragma unroll
        for (int j = 0; j < 4; j++) { am[i][j] = 0.0f; al[i][j] = 0.0f; }

    const float4* wm4 = (const float4*)Wm;   // [DD][ADIM]: row k -> 16 float4
    const float4* wl4 = (const float4*)Wl;

    #pragma unroll 4
    for (int k = 0; k < DD; k++) {
        float a0 = Qs[(ty * 4 + 0) * QPAD + k];
        float a1 = Qs[(ty * 4 + 1) * QPAD + k];
        float a2 = Qs[(ty * 4 + 2) * QPAD + k];
        float a3 = Qs[(ty * 4 + 3) * QPAD + k];
        float4 m4 = wm4[k * 16 + tx];
        float4 l4 = wl4[k * 16 + tx];
        #define PR_UPD(ai, ii)                                                 \
            am[ii][0] += ai * m4.x; am[ii][1] += ai * m4.y;                    \
            am[ii][2] += ai * m4.z; am[ii][3] += ai * m4.w;                    \
            al[ii][0] += ai * l4.x; al[ii][1] += ai * l4.y;                    \
            al[ii][2] += ai * l4.z; al[ii][3] += ai * l4.w;
        PR_UPD(a0, 0) PR_UPD(a1, 1) PR_UPD(a2, 2) PR_UPD(a3, 3)
        #undef PR_UPD
    }

    // ---- epilogue: biases, reparameterize, store 3 outputs ----
    const size_t BSA = (size_t)BB * SS * ADIM;
    float4 bm4 = ((const float4*)bm)[tx];
    float4 bl4 = ((const float4*)bl)[tx];

    #pragma unroll
    for (int i = 0; i < 4; i++) {
        int row = qt * BM + ty * 4 + i;
        size_t base = (((size_t)b * SS + row) * ADIM) + tx * 4;
        float4 e4 = *((const float4*)(eps + base));

        float4 mo, lo, ao;
        mo.x = am[i][0] + bm4.x;  mo.y = am[i][1] + bm4.y;
        mo.z = am[i][2] + bm4.z;  mo.w = am[i][3] + bm4.w;
        lo.x = al[i][0] + bl4.x;  lo.y = al[i][1] + bl4.y;
        lo.z = al[i][2] + bl4.z;  lo.w = al[i][3] + bl4.w;
        ao.x = mo.x + __expf(0.5f * lo.x) * e4.x;
        ao.y = mo.y + __expf(0.5f * lo.y) * e4.y;
        ao.z = mo.z + __expf(0.5f * lo.z) * e4.z;
        ao.w = mo.w + __expf(0.5f * lo.w) * e4.w;

        *((float4*)(out + base))           = mo;
        *((float4*)(out + BSA + base))     = lo;
        *((float4*)(out + 2 * BSA + base)) = ao;
    }
}

extern "C" void kernel_launch(void* const* d_in, const int* in_sizes, int n_in,
                              void* d_out, int out_size)
{
    const float* x   = (const float*)d_in[0];
    const float* Wm  = (const float*)d_in[1];
    const float* bm  = (const float*)d_in[2];
    const float* Wl  = (const float*)d_in[3];
    const float* bl  = (const float*)d_in[4];
    const float* eps = (const float*)d_in[5];
    float* out = (float*)d_out;

    cudaFuncSetAttribute(vs_attn_vae_kernel,
                         cudaFuncAttributeMaxDynamicSharedMemorySize, SMEM_BYTES);

    dim3 grid(SS / BM, BB);
    vs_attn_vae_kernel<<<grid, THREADS, SMEM_BYTES>>>(x, Wm, bm, Wl, bl, eps, out);
}

// round 7
// speedup vs baseline: 2.1395x; 1.0014x over previous
#include <cuda_runtime.h>
#include <cstdint>

// Problem constants
#define BB    8
#define SS    2048
#define DD    256
#define ADIM  64

#define BM      64
#define BN      64
#define THREADS 256
#define QPAD    260         // floats/row; 260 mod 32 = 4 (bank stagger), 16B-aligned rows
#define PPAD    68          // 68 mod 32 = 4
#define NTILES  (SS / BN)

// smem: Q (BM x QPAD) | K0 (BN x QPAD) | K1 (BN x QPAD) | P (BM x PPAD)
#define SMEM_FLOATS (3 * BM * QPAD + BM * PPAD)
#define SMEM_BYTES  (SMEM_FLOATS * 4)

__device__ __forceinline__ void cp_async16(uint32_t saddr, const void* gptr) {
    asm volatile("cp.async.cg.shared.global [%0], [%1], 16;\n" :: "r"(saddr), "l"(gptr));
}
__device__ __forceinline__ void cp_commit() { asm volatile("cp.async.commit_group;\n" ::: "memory"); }
__device__ __forceinline__ void cp_wait0()  { asm volatile("cp.async.wait_group 0;\n" ::: "memory"); }

__global__ __launch_bounds__(THREADS, 1)
void vs_attn_vae_kernel(const float* __restrict__ x,
                        const float* __restrict__ Wm,
                        const float* __restrict__ bm,
                        const float* __restrict__ Wl,
                        const float* __restrict__ bl,
                        const float* __restrict__ eps,
                        float* __restrict__ out)
{
    extern __shared__ float smem[];
    float* Qs = smem;                               // [BM][QPAD]; reused as A_det
    float* K0 = smem + BM * QPAD;
    float* K1 = smem + 2 * BM * QPAD;
    float* Ps = smem + 3 * BM * QPAD;               // [BM][PPAD]

    const int b  = blockIdx.y;
    const int qt = blockIdx.x;
    const int t  = threadIdx.x;
    const int ty = t >> 4;                          // 0..15
    const int tx = t & 15;                          // 0..15

    const float* xb = x + (size_t)b * SS * DD;

    // --- prefetch helpers: 16 x 16B per thread per 64x256 tile ---
    auto issue_tile = [&](const float* src, float* dst) {
        #pragma unroll
        for (int k = 0; k < 16; k++) {
            int i  = t + k * THREADS;               // 0..4095 float4 slots
            int r  = i >> 6;
            int c4 = i & 63;
            uint32_t saddr = (uint32_t)__cvta_generic_to_shared(dst + r * QPAD + c4 * 4);
            cp_async16(saddr, src + i * 4);
        }
        cp_commit();
    };

    // prefetch K tile 0 and Q tile (one group; wait once)
    issue_tile(xb, K0);
    issue_tile(xb + (size_t)qt * BM * DD, Qs);
    cp_wait0();
    __syncthreads();

    float acc[4][16];   // rows ty*4+i ; cols 4*tx + 64*g + c  -> acc[i][g*4+c]
    #pragma unroll
    for (int i = 0; i < 4; i++)
        #pragma unroll
        for (int j = 0; j < 16; j++) acc[i][j] = 0.0f;

    float rs[4] = {0.f, 0.f, 0.f, 0.f};
    const float scale = 0.0625f;

    for (int kt = 0; kt < NTILES; kt++) {
        float* cur = (kt & 1) ? K1 : K0;
        if (kt + 1 < NTILES)
            issue_tile(xb + (size_t)(kt + 1) * BN * DD, (kt & 1) ? K0 : K1);

        // ---- S = Q K^T : rows ty*4+i, key rows tx+16j (conflict-free) ----
        float s[4][4];
        #pragma unroll
        for (int i = 0; i < 4; i++)
            #pragma unroll
            for (int j = 0; j < 4; j++) s[i][j] = 0.0f;

        #pragma unroll 2
        for (int kk = 0; kk < DD / 4; kk++) {
            float4 qv[4], kv[4];
            #pragma unroll
            for (int i = 0; i < 4; i++)
                qv[i] = ((const float4*)(Qs + (ty * 4 + i) * QPAD))[kk];
            #pragma unroll
            for (int j = 0; j < 4; j++)
                kv[j] = ((const float4*)(cur + (tx + 16 * j) * QPAD))[kk];
            #pragma unroll
            for (int i = 0; i < 4; i++)
                #pragma unroll
                for (int j = 0; j < 4; j++)
                    s[i][j] += qv[i].x * kv[j].x + qv[i].y * kv[j].y
                             + qv[i].z * kv[j].z + qv[i].w * kv[j].w;
        }

        // ---- P = exp(S/16); row-sum partials; stage P (conflict-free) ----
        #pragma unroll
        for (int i = 0; i < 4; i++) {
            #pragma unroll
            for (int j = 0; j < 4; j++) {
                float p = __expf(s[i][j] * scale);
                rs[i] += p;
                Ps[(ty * 4 + i) * PPAD + tx + 16 * j] = p;
            }
        }
        __syncthreads();

        // ---- acc += P @ V : V cols 4tx+64g (conflict-free float4) ----
        #pragma unroll 2
        for (int n = 0; n < BN; n++) {
            float p0 = Ps[(ty * 4 + 0) * PPAD + n];
            float p1 = Ps[(ty * 4 + 1) * PPAD + n];
            float p2 = Ps[(ty * 4 + 2) * PPAD + n];
            float p3 = Ps[(ty * 4 + 3) * PPAD + n];
            const float4* vr = (const float4*)(cur + n * QPAD);
            float4 v0 = vr[tx +  0];
            float4 v1 = vr[tx + 16];
            float4 v2 = vr[tx + 32];
            float4 v3 = vr[tx + 48];
            #define PV_UPD(pi, ii)                                             \
                acc[ii][0]  += pi * v0.x; acc[ii][1]  += pi * v0.y;            \
                acc[ii][2]  += pi * v0.z; acc[ii][3]  += pi * v0.w;            \
                acc[ii][4]  += pi * v1.x; acc[ii][5]  += pi * v1.y;            \
                acc[ii][6]  += pi * v1.z; acc[ii][7]  += pi * v1.w;            \
                acc[ii][8]  += pi * v2.x; acc[ii][9]  += pi * v2.y;            \
                acc[ii][10] += pi * v2.z; acc[ii][11] += pi * v2.w;            \
                acc[ii][12] += pi * v3.x; acc[ii][13] += pi * v3.y;            \
                acc[ii][14] += pi * v3.z; acc[ii][15] += pi * v3.w;
            PV_UPD(p0, 0) PV_UPD(p1, 1) PV_UPD(p2, 2) PV_UPD(p3, 3)
            #undef PV_UPD
        }

        if (kt + 1 < NTILES) cp_wait0();
        __syncthreads();    // PV done with cur/Ps; next K buffer fully landed
    }

    // ---- finalize row sums: thread's cols tx+16j; reduce across 16 tx lanes ----
    #pragma unroll
    for (int m = 1; m < 16; m <<= 1) {
        #pragma unroll
        for (int i = 0; i < 4; i++)
            rs[i] += __shfl_xor_sync(0xffffffffu, rs[i], m);
    }

    // ---- normalize; stage A_det into Qs (conflict-free float4 stores) ----
    #pragma unroll
    for (int i = 0; i < 4; i++) {
        float inv = 1.0f / rs[i];
        #pragma unroll
        for (int g = 0; g < 4; g++) {
            float4 v;
            v.x = acc[i][g * 4 + 0] * inv;
            v.y = acc[i][g * 4 + 1] * inv;
            v.z = acc[i][g * 4 + 2] * inv;
            v.w = acc[i][g * 4 + 3] * inv;
            ((float4*)(Qs + (ty * 4 + i) * QPAD))[tx + 16 * g] = v;
        }
    }
    __syncthreads();

    // ---- projections: A_mean / A_logvar ----
    float am[4][4], al[4][4];
    #pragma unroll
    for (int i = 0; i < 4; i++)
        #pragma unroll
        for (int j = 0; j < 4; j++) { am[i][j] = 0.0f; al[i][j] = 0.0f; }

    const float4* wm4 = (const float4*)Wm;   // [DD][ADIM]: row k -> 16 float4
    const float4* wl4 = (const float4*)Wl;

    #pragma unroll 4
    for (int k = 0; k < DD; k++) {
        float a0 = Qs[(ty * 4 + 0) * QPAD + k];
        float a1 = Qs[(ty * 4 + 1) * QPAD + k];
        float a2 = Qs[(ty * 4 + 2) * QPAD + k];
        float a3 = Qs[(ty * 4 + 3) * QPAD + k];
        float4 m4 = wm4[k * 16 + tx];
        float4 l4 = wl4[k * 16 + tx];
        #define PR_UPD(ai, ii)                                                 \
            am[ii][0] += ai * m4.x; am[ii][1] += ai * m4.y;                    \
            am[ii][2] += ai * m4.z; am[ii][3] += ai * m4.w;                    \
            al[ii][0] += ai * l4.x; al[ii][1] += ai * l4.y;                    \
            al[ii][2] += ai * l4.z; al[ii][3] += ai * l4.w;
        PR_UPD(a0, 0) PR_UPD(a1, 1) PR_UPD(a2, 2) PR_UPD(a3, 3)
        #undef PR_UPD
    }

    // ---- epilogue: biases, reparameterize, store 3 outputs ----
    const size_t BSA = (size_t)BB * SS * ADIM;
    float4 bm4 = ((const float4*)bm)[tx];
    float4 bl4 = ((const float4*)bl)[tx];

    #pragma unroll
    for (int i = 0; i < 4; i++) {
        int row = qt * BM + ty * 4 + i;
        size_t base = (((size_t)b * SS + row) * ADIM) + tx * 4;
        float4 e4 = *((const float4*)(eps + base));

        float4 mo, lo, ao;
        mo.x = am[i][0] + bm4.x;  mo.y = am[i][1] + bm4.y;
        mo.z = am[i][2] + bm4.z;  mo.w = am[i][3] + bm4.w;
        lo.x = al[i][0] + bl4.x;  lo.y = al[i][1] + bl4.y;
        lo.z = al[i][2] + bl4.z;  lo.w = al[i][3] + bl4.w;
        ao.x = mo.x + __expf(0.5f * lo.x) * e4.x;
        ao.y = mo.y + __expf(0.5f * lo.y) * e4.y;
        ao.z = mo.z + __expf(0.5f * lo.z) * e4.z;
        ao.w = mo.w + __expf(0.5f * lo.w) * e4.w;

        *((float4*)(out + base))           = mo;
        *((float4*)(out + BSA + base))     = lo;
        *((float4*)(out + 2 * BSA + base)) = ao;
    }
}

extern "C" void kernel_launch(void* const* d_in, const int* in_sizes, int n_in,
                              void* d_out, int out_size)
{
    const float* x   = (const float*)d_in[0];
    const float* Wm  = (const float*)d_in[1];
    const float* bm  = (const float*)d_in[2];
    const float* Wl  = (const float*)d_in[3];
    const float* bl  = (const float*)d_in[4];
    const float* eps = (const float*)d_in[5];
    float* out = (float*)d_out;

    cudaFuncSetAttribute(vs_attn_vae_kernel,
                         cudaFuncAttributeMaxDynamicSharedMemorySize, SMEM_BYTES);

    dim3 grid(SS / BM, BB);
    vs_attn_vae_kernel<<<grid, THREADS, SMEM_BYTES>>>(x, Wm, bm, Wl, bl, eps, out);
}

// round 11
// speedup vs baseline: 5.3996x; 2.5238x over previous
#include <cuda_runtime.h>
#include <cuda_bf16.h>
#include <cstdint>

#define BB 8
#define SS 2048
#define DD 256
#define ADIM 64
#define BM 64
#define BN 32
#define NT 64          // SS/BN
#define THREADS 256

#define XS 264         // Q/K smem row stride (bf16 elems) = 528B
#define PSTR 56        // P smem row stride (bf16) = 112B

// smem byte offsets
#define SM_QHI 0
#define SM_QLO 33792
#define SM_KHI 67584
#define SM_KLO 84480
#define SM_PHI 101376
#define SM_PLO 108544
#define SM_RS  115712
#define SMEM_BYTES 116224

#define LDSM4(r, a) \
    asm volatile("ldmatrix.sync.aligned.m8n8.x4.shared.b16 {%0,%1,%2,%3}, [%4];" \
                 : "=r"((r)[0]), "=r"((r)[1]), "=r"((r)[2]), "=r"((r)[3]) : "r"(a))
#define LDSM4T(r, a) \
    asm volatile("ldmatrix.sync.aligned.m8n8.x4.trans.shared.b16 {%0,%1,%2,%3}, [%4];" \
                 : "=r"((r)[0]), "=r"((r)[1]), "=r"((r)[2]), "=r"((r)[3]) : "r"(a))

__device__ __forceinline__ void mma16816(float* c, const uint32_t* a, uint32_t b0, uint32_t b1) {
    asm volatile("mma.sync.aligned.m16n8k16.row.col.f32.bf16.bf16.f32 "
                 "{%0,%1,%2,%3}, {%4,%5,%6,%7}, {%8,%9}, {%0,%1,%2,%3};"
                 : "+f"(c[0]), "+f"(c[1]), "+f"(c[2]), "+f"(c[3])
                 : "r"(a[0]), "r"(a[1]), "r"(a[2]), "r"(a[3]), "r"(b0), "r"(b1));
}

__device__ __forceinline__ uint32_t smem_u32(const void* p) {
    uint32_t a;
    asm("{ .reg .u64 t; cvta.to.shared.u64 t, %1; cvt.u32.u64 %0, t; }" : "=r"(a) : "l"(p));
    return a;
}

// split (a,b) fp32 -> packed bf16x2 hi and lo
__device__ __forceinline__ void split2(float a, float b, uint32_t& hi, uint32_t& lo) {
    __nv_bfloat162 h = __floats2bfloat162_rn(a, b);
    __nv_bfloat162 l = __floats2bfloat162_rn(a - __bfloat162float(h.x), b - __bfloat162float(h.y));
    hi = *reinterpret_cast<uint32_t*>(&h);
    lo = *reinterpret_cast<uint32_t*>(&l);
}

// convert rows x 256 fp32 tile -> bf16 hi/lo smem (row stride XS)
__device__ __forceinline__ void conv_tile(const float* __restrict__ src, char* hi, char* lo,
                                          int nf4, int t) {
    for (int idx = t; idx < nf4; idx += THREADS) {
        int r = idx >> 6, f4 = idx & 63;
        float4 v = ((const float4*)src)[idx];
        uint32_t h0, l0, h1, l1;
        split2(v.x, v.y, h0, l0);
        split2(v.z, v.w, h1, l1);
        uint32_t byte = (uint32_t)r * (XS * 2) + (uint32_t)f4 * 8;
        *(uint32_t*)(hi + byte) = h0;  *(uint32_t*)(hi + byte + 4) = h1;
        *(uint32_t*)(lo + byte) = l0;  *(uint32_t*)(lo + byte + 4) = l1;
    }
}

__global__ __launch_bounds__(THREADS, 1)
void vs_mma_kernel(const float* __restrict__ x,
                   const float* __restrict__ Wm, const float* __restrict__ bmb,
                   const float* __restrict__ Wl, const float* __restrict__ blb,
                   const float* __restrict__ eps, float* __restrict__ out)
{
    extern __shared__ __align__(128) char smem[];
    const int b = blockIdx.y, qt = blockIdx.x, t = threadIdx.x;
    const int w = t >> 5, lane = t & 31;
    const int rg = w & 3;          // row group (16 rows)
    const int cg = w >> 2;         // col group (S) / feature half (PV)
    const int quad = lane & 3;
    const float* xb = x + (size_t)b * SS * DD;

    // prologue: convert Q tile (64x256)
    conv_tile(xb + (size_t)qt * BM * DD, smem + SM_QHI, smem + SM_QLO, BM * 64, t);

    const uint32_t sQhi = smem_u32(smem + SM_QHI), sQlo = smem_u32(smem + SM_QLO);
    const uint32_t sKhi = smem_u32(smem + SM_KHI), sKlo = smem_u32(smem + SM_KLO);
    const uint32_t sPhi = smem_u32(smem + SM_PHI), sPlo = smem_u32(smem + SM_PLO);

    // ldmatrix per-lane address offsets
    const int lrow = ((lane >> 3) & 1) * 8 + (lane & 7);   // tile row within 16
    const int lcol = (lane >> 4) * 16;                     // +8 elems (bytes)
    const uint32_t aoff = (uint32_t)(rg * 16 + lrow) * (XS * 2) + lcol;   // Q / P rows
    const uint32_t boff = (uint32_t)(cg * 16 + lrow) * (XS * 2) + lcol;   // K rows (S phase)
    const uint32_t paoff = (uint32_t)(rg * 16 + lrow) * (PSTR * 2) + lcol;
    const uint32_t vcol = (uint32_t)(cg * 256 + (lane >> 4) * 16);        // PV feat half base
    const uint32_t vrow0 = (uint32_t)lrow * (XS * 2);

    float o[16][4];
    #pragma unroll
    for (int i = 0; i < 16; i++)
        #pragma unroll
        for (int j = 0; j < 4; j++) o[i][j] = 0.f;
    float rs0 = 0.f, rs1 = 0.f;

    for (int kt = 0; kt < NT; kt++) {
        __syncthreads();                       // prior PV done reading K
        conv_tile(xb + (size_t)kt * BN * DD, smem + SM_KHI, smem + SM_KLO, BN * 64, t);
        __syncthreads();

        // ---- S = Q K^T (16x16 per warp), bf16x3 ----
        float sc[2][4] = {{0.f, 0.f, 0.f, 0.f}, {0.f, 0.f, 0.f, 0.f}};
        #pragma unroll
        for (int ks = 0; ks < 16; ks++) {
            uint32_t aH[4], aL[4], bH[4], bL[4];
            LDSM4(aH, sQhi + aoff + ks * 32);
            LDSM4(aL, sQlo + aoff + ks * 32);
            LDSM4(bH, sKhi + boff + ks * 32);
            LDSM4(bL, sKlo + boff + ks * 32);
            mma16816(sc[0], aH, bH[0], bH[2]);
            mma16816(sc[0], aH, bL[0], bL[2]);
            mma16816(sc[0], aL, bH[0], bH[2]);
            mma16816(sc[1], aH, bH[1], bH[3]);
            mma16816(sc[1], aH, bL[1], bL[3]);
            mma16816(sc[1], aL, bH[1], bH[3]);
        }

        // ---- softmax numerators, rowsum partials, stage P hi/lo ----
        const int prow0 = rg * 16 + (lane >> 2);
        #pragma unroll
        for (int nt = 0; nt < 2; nt++) {
            float p0 = __expf(sc[nt][0] * 0.0625f);
            float p1 = __expf(sc[nt][1] * 0.0625f);
            float p2 = __expf(sc[nt][2] * 0.0625f);
            float p3 = __expf(sc[nt][3] * 0.0625f);
            rs0 += p0 + p1;  rs1 += p2 + p3;
            uint32_t h0, l0, h1, l1;
            split2(p0, p1, h0, l0);
            split2(p2, p3, h1, l1);
            uint32_t cb = (uint32_t)(cg * 16 + nt * 8 + 2 * quad) * 2;
            *(uint32_t*)(smem + SM_PHI + prow0 * (PSTR * 2) + cb) = h0;
            *(uint32_t*)(smem + SM_PLO + prow0 * (PSTR * 2) + cb) = l0;
            *(uint32_t*)(smem + SM_PHI + (prow0 + 8) * (PSTR * 2) + cb) = h1;
            *(uint32_t*)(smem + SM_PLO + (prow0 + 8) * (PSTR * 2) + cb) = l1;
        }
        __syncthreads();

        // ---- O += P V : warp = 16 rows x 128 feats (cg half), bf16x3 ----
        #pragma unroll
        for (int ks = 0; ks < 2; ks++) {
            uint32_t pH[4], pL[4];
            LDSM4(pH, sPhi + paoff + ks * 32);
            LDSM4(pL, sPlo + paoff + ks * 32);
            #pragma unroll
            for (int np = 0; np < 8; np++) {
                uint32_t vH[4], vL[4];
                uint32_t va = (uint32_t)(ks * 16) * (XS * 2) + vrow0 + vcol + np * 32;
                LDSM4T(vH, sKhi + va);
                LDSM4T(vL, sKlo + va);
                mma16816(o[np * 2], pH, vH[0], vH[1]);
                mma16816(o[np * 2], pH, vL[0], vL[1]);
                mma16816(o[np * 2], pL, vH[0], vH[1]);
                mma16816(o[np * 2 + 1], pH, vH[2], vH[3]);
                mma16816(o[np * 2 + 1], pH, vL[2], vL[3]);
                mma16816(o[np * 2 + 1], pL, vH[2], vH[3]);
            }
        }
    }

    // ---- rowsum reduce: quads, then the 2 col-groups via smem ----
    rs0 += __shfl_xor_sync(0xffffffffu, rs0, 1);
    rs0 += __shfl_xor_sync(0xffffffffu, rs0, 2);
    rs1 += __shfl_xor_sync(0xffffffffu, rs1, 1);
    rs1 += __shfl_xor_sync(0xffffffffu, rs1, 2);
    float* rsm = (float*)(smem + SM_RS);       // [2][64]
    if (quad == 0) {
        rsm[cg * 64 + rg * 16 + (lane >> 2)] = rs0;
        rsm[cg * 64 + rg * 16 + (lane >> 2) + 8] = rs1;
    }
    __syncthreads();

    const int orow0 = rg * 16 + (lane >> 2);
    float inv0 = 1.f / (rsm[orow0] + rsm[64 + orow0]);
    float inv1 = 1.f / (rsm[orow0 + 8] + rsm[64 + orow0 + 8]);
    __syncthreads();                            // all reads done before Ad overwrites smem

    // ---- A_det fp32 -> smem [64][260] (reuses Q region) ----
    float* Ad = (float*)smem;
    #pragma unroll
    for (int nt = 0; nt < 16; nt++) {
        int col = cg * 128 + nt * 8 + 2 * quad;
        Ad[orow0 * 260 + col] = o[nt][0] * inv0;
        Ad[orow0 * 260 + col + 1] = o[nt][1] * inv0;
        Ad[(orow0 + 8) * 260 + col] = o[nt][2] * inv1;
        Ad[(orow0 + 8) * 260 + col + 1] = o[nt][3] * inv1;
    }
    __syncthreads();

    // ---- SIMT projections + reparam epilogue (rows ty*4+i, cols tx*4) ----
    const int ty = t >> 4, tx = t & 15;
    float am[4][4], al[4][4];
    #pragma unroll
    for (int i = 0; i < 4; i++)
        #pragma unroll
        for (int j = 0; j < 4; j++) { am[i][j] = 0.f; al[i][j] = 0.f; }

    const float4* wm4 = (const float4*)Wm;
    const float4* wl4 = (const float4*)Wl;
    #pragma unroll 4
    for (int k = 0; k < DD; k++) {
        float4 m4 = wm4[k * 16 + tx];
        float4 l4 = wl4[k * 16 + tx];
        #pragma unroll
        for (int i = 0; i < 4; i++) {
            float a = Ad[(ty * 4 + i) * 260 + k];
            am[i][0] += a * m4.x; am[i][1] += a * m4.y; am[i][2] += a * m4.z; am[i][3] += a * m4.w;
            al[i][0] += a * l4.x; al[i][1] += a * l4.y; al[i][2] += a * l4.z; al[i][3] += a * l4.w;
        }
    }

    const size_t BSA = (size_t)BB * SS * ADIM;
    float4 bm4 = ((const float4*)bmb)[tx];
    float4 bl4 = ((const float4*)blb)[tx];
    #pragma unroll
    for (int i = 0; i < 4; i++) {
        int row = qt * BM + ty * 4 + i;
        size_t base = (((size_t)b * SS + row) * ADIM) + tx * 4;
        float4 e4 = *((const float4*)(eps + base));
        float4 mo, lo, ao;
        mo.x = am[i][0] + bm4.x; mo.y = am[i][1] + bm4.y; mo.z = am[i][2] + bm4.z; mo.w = am[i][3] + bm4.w;
        lo.x = al[i][0] + bl4.x; lo.y = al[i][1] + bl4.y; lo.z = al[i][2] + bl4.z; lo.w = al[i][3] + bl4.w;
        ao.x = mo.x + __expf(0.5f * lo.x) * e4.x;
        ao.y = mo.y + __expf(0.5f * lo.y) * e4.y;
        ao.z = mo.z + __expf(0.5f * lo.z) * e4.z;
        ao.w = mo.w + __expf(0.5f * lo.w) * e4.w;
        *((float4*)(out + base)) = mo;
        *((float4*)(out + BSA + base)) = lo;
        *((float4*)(out + 2 * BSA + base)) = ao;
    }
}

extern "C" void kernel_launch(void* const* d_in, const int* in_sizes, int n_in,
                              void* d_out, int out_size)
{
    const float* x   = (const float*)d_in[0];
    const float* Wm  = (const float*)d_in[1];
    const float* bmb = (const float*)d_in[2];
    const float* Wl  = (const float*)d_in[3];
    const float* blb = (const float*)d_in[4];
    const float* eps = (const float*)d_in[5];
    cudaFuncSetAttribute(vs_mma_kernel, cudaFuncAttributeMaxDynamicSharedMemorySize, SMEM_BYTES);
    dim3 grid(SS / BM, BB);
    vs_mma_kernel<<<grid, THREADS, SMEM_BYTES>>>(x, Wm, bmb, Wl, blb, eps, (float*)d_out);
}

// round 12
// speedup vs baseline: 5.9013x; 1.0929x over previous
#include <cuda_runtime.h>
#include <cuda_bf16.h>
#include <cstdint>

#define BB 8
#define SS 2048
#define DD 256
#define ADIM 64
#define BM 64
#define BN 32
#define NT 64          // SS/BN
#define THREADS 256

#define XS 264         // smem row stride (bf16 elems) = 528B
#define PSTR 56        // P smem row stride (bf16) = 112B

// smem byte offsets
#define SM_QHI 0
#define SM_QLO 33792
#define SM_K0  67584            // hi +0 (16896B), lo +16896
#define SM_K1  101376
#define SM_PHI 135168
#define SM_PLO 142336
#define SM_RS  149504
#define SMEM_BYTES 150016

// pre-split x in bf16 (persistent device scratch; static allocation)
__device__ __nv_bfloat16 g_xhi[BB * SS * DD];
__device__ __nv_bfloat16 g_xlo[BB * SS * DD];

#define LDSM4(r, a) \
    asm volatile("ldmatrix.sync.aligned.m8n8.x4.shared.b16 {%0,%1,%2,%3}, [%4];" \
                 : "=r"((r)[0]), "=r"((r)[1]), "=r"((r)[2]), "=r"((r)[3]) : "r"(a))
#define LDSM4T(r, a) \
    asm volatile("ldmatrix.sync.aligned.m8n8.x4.trans.shared.b16 {%0,%1,%2,%3}, [%4];" \
                 : "=r"((r)[0]), "=r"((r)[1]), "=r"((r)[2]), "=r"((r)[3]) : "r"(a))

__device__ __forceinline__ void mma16816(float* c, const uint32_t* a, uint32_t b0, uint32_t b1) {
    asm volatile("mma.sync.aligned.m16n8k16.row.col.f32.bf16.bf16.f32 "
                 "{%0,%1,%2,%3}, {%4,%5,%6,%7}, {%8,%9}, {%0,%1,%2,%3};"
                 : "+f"(c[0]), "+f"(c[1]), "+f"(c[2]), "+f"(c[3])
                 : "r"(a[0]), "r"(a[1]), "r"(a[2]), "r"(a[3]), "r"(b0), "r"(b1));
}

__device__ __forceinline__ uint32_t smem_u32(const void* p) {
    uint32_t a;
    asm("{ .reg .u64 t; cvta.to.shared.u64 t, %1; cvt.u32.u64 %0, t; }" : "=r"(a) : "l"(p));
    return a;
}
__device__ __forceinline__ void cp_async16(uint32_t saddr, const void* gptr) {
    asm volatile("cp.async.cg.shared.global [%0], [%1], 16;\n" :: "r"(saddr), "l"(gptr));
}
__device__ __forceinline__ void cp_commit() { asm volatile("cp.async.commit_group;\n" ::: "memory"); }
__device__ __forceinline__ void cp_wait0()  { asm volatile("cp.async.wait_group 0;\n" ::: "memory"); }

__device__ __forceinline__ void split2(float a, float b, uint32_t& hi, uint32_t& lo) {
    __nv_bfloat162 h = __floats2bfloat162_rn(a, b);
    __nv_bfloat162 l = __floats2bfloat162_rn(a - __bfloat162float(h.x), b - __bfloat162float(h.y));
    hi = *reinterpret_cast<uint32_t*>(&h);
    lo = *reinterpret_cast<uint32_t*>(&l);
}

// ---------------- kernel A: x fp32 -> bf16 hi/lo split ----------------
__global__ __launch_bounds__(256, 4)
void vs_conv_kernel(const float* __restrict__ x)
{
    int i = blockIdx.x * 256 + threadIdx.x;      // float4 index; grid covers all
    float4 v = ((const float4*)x)[i];
    uint32_t h0, l0, h1, l1;
    split2(v.x, v.y, h0, l0);
    split2(v.z, v.w, h1, l1);
    uint2 h; h.x = h0; h.y = h1;
    uint2 l; l.x = l0; l.y = l1;
    ((uint2*)g_xhi)[i] = h;
    ((uint2*)g_xlo)[i] = l;
}

// ---------------- kernel B: attention + projections ----------------
__global__ __launch_bounds__(THREADS, 1)
void vs_mma_kernel(const float* __restrict__ Wm, const float* __restrict__ bmb,
                   const float* __restrict__ Wl, const float* __restrict__ blb,
                   const float* __restrict__ eps, float* __restrict__ out)
{
    extern __shared__ __align__(128) char smem[];
    const int b = blockIdx.y, qt = blockIdx.x, t = threadIdx.x;
    const int w = t >> 5, lane = t & 31;
    const int rg = w & 3;          // row group (16 rows)
    const int cg = w >> 2;         // col group (S) / feature half (PV)
    const int quad = lane & 3;

    const char* gxh = (const char*)g_xhi + (size_t)b * SS * DD * 2;
    const char* gxl = (const char*)g_xlo + (size_t)b * SS * DD * 2;

    // prologue: async-load Q tile (64 rows) hi/lo
    {
        const char* qh = gxh + (size_t)qt * BM * DD * 2;
        const char* ql = gxl + (size_t)qt * BM * DD * 2;
        #pragma unroll
        for (int k = 0; k < 8; k++) {
            int i = t + k * THREADS;            // 2048 chunks of 16B
            int r = i >> 5, c = i & 31;
            cp_async16(smem_u32(smem + SM_QHI + r * 528 + c * 16), qh + r * 512 + c * 16);
            cp_async16(smem_u32(smem + SM_QLO + r * 528 + c * 16), ql + r * 512 + c * 16);
        }
        // K tile 0
        #pragma unroll
        for (int k = 0; k < 4; k++) {
            int i = t + k * THREADS;            // 1024 chunks
            int r = i >> 5, c = i & 31;
            cp_async16(smem_u32(smem + SM_K0 + r * 528 + c * 16), gxh + r * 512 + c * 16);
            cp_async16(smem_u32(smem + SM_K0 + 16896 + r * 528 + c * 16), gxl + r * 512 + c * 16);
        }
        cp_commit();
        cp_wait0();
    }
    __syncthreads();

    const uint32_t sQhi = smem_u32(smem + SM_QHI), sQlo = smem_u32(smem + SM_QLO);
    const uint32_t sPhi = smem_u32(smem + SM_PHI), sPlo = smem_u32(smem + SM_PLO);

    // ldmatrix per-lane address offsets
    const int lrow = ((lane >> 3) & 1) * 8 + (lane & 7);
    const int lcol = (lane >> 4) * 16;
    const uint32_t aoff = (uint32_t)(rg * 16 + lrow) * (XS * 2) + lcol;
    const uint32_t boff = (uint32_t)(cg * 16 + lrow) * (XS * 2) + lcol;
    const uint32_t paoff = (uint32_t)(rg * 16 + lrow) * (PSTR * 2) + lcol;
    const uint32_t vcol = (uint32_t)(cg * 256 + (lane >> 4) * 16);
    const uint32_t vrow0 = (uint32_t)lrow * (XS * 2);

    float o[16][4];
    #pragma unroll
    for (int i = 0; i < 16; i++)
        #pragma unroll
        for (int j = 0; j < 4; j++) o[i][j] = 0.f;
    float rs0 = 0.f, rs1 = 0.f;

    for (int kt = 0; kt < NT; kt++) {
        const uint32_t kb = (kt & 1) ? SM_K1 : SM_K0;
        // prefetch next K tile into the other buffer
        if (kt + 1 < NT) {
            const uint32_t nb = (kt & 1) ? SM_K0 : SM_K1;
            const char* kh = gxh + (size_t)(kt + 1) * BN * DD * 2;
            const char* kl = gxl + (size_t)(kt + 1) * BN * DD * 2;
            #pragma unroll
            for (int k = 0; k < 4; k++) {
                int i = t + k * THREADS;
                int r = i >> 5, c = i & 31;
                cp_async16(smem_u32(smem + nb + r * 528 + c * 16), kh + r * 512 + c * 16);
                cp_async16(smem_u32(smem + nb + 16896 + r * 528 + c * 16), kl + r * 512 + c * 16);
            }
            cp_commit();
        }
        const uint32_t sKhi = smem_u32(smem + kb), sKlo = smem_u32(smem + kb + 16896);

        // ---- S = Q K^T (16x16 per warp), bf16x3 ----
        float sc[2][4] = {{0.f, 0.f, 0.f, 0.f}, {0.f, 0.f, 0.f, 0.f}};
        #pragma unroll
        for (int ks = 0; ks < 16; ks++) {
            uint32_t aH[4], aL[4], bH[4], bL[4];
            LDSM4(aH, sQhi + aoff + ks * 32);
            LDSM4(aL, sQlo + aoff + ks * 32);
            LDSM4(bH, sKhi + boff + ks * 32);
            LDSM4(bL, sKlo + boff + ks * 32);
            mma16816(sc[0], aH, bH[0], bH[2]);
            mma16816(sc[0], aH, bL[0], bL[2]);
            mma16816(sc[0], aL, bH[0], bH[2]);
            mma16816(sc[1], aH, bH[1], bH[3]);
            mma16816(sc[1], aH, bL[1], bL[3]);
            mma16816(sc[1], aL, bH[1], bH[3]);
        }

        // ---- softmax numerators, rowsum partials, stage P hi/lo ----
        const int prow0 = rg * 16 + (lane >> 2);
        #pragma unroll
        for (int nt = 0; nt < 2; nt++) {
            float p0 = __expf(sc[nt][0] * 0.0625f);
            float p1 = __expf(sc[nt][1] * 0.0625f);
            float p2 = __expf(sc[nt][2] * 0.0625f);
            float p3 = __expf(sc[nt][3] * 0.0625f);
            rs0 += p0 + p1;  rs1 += p2 + p3;
            uint32_t h0, l0, h1, l1;
            split2(p0, p1, h0, l0);
            split2(p2, p3, h1, l1);
            uint32_t cb = (uint32_t)(cg * 16 + nt * 8 + 2 * quad) * 2;
            *(uint32_t*)(smem + SM_PHI + prow0 * (PSTR * 2) + cb) = h0;
            *(uint32_t*)(smem + SM_PLO + prow0 * (PSTR * 2) + cb) = l0;
            *(uint32_t*)(smem + SM_PHI + (prow0 + 8) * (PSTR * 2) + cb) = h1;
            *(uint32_t*)(smem + SM_PLO + (prow0 + 8) * (PSTR * 2) + cb) = l1;
        }
        __syncthreads();

        // ---- O += P V : warp = 16 rows x 128 feats (cg half), bf16x3 ----
        #pragma unroll
        for (int ks = 0; ks < 2; ks++) {
            uint32_t pH[4], pL[4];
            LDSM4(pH, sPhi + paoff + ks * 32);
            LDSM4(pL, sPlo + paoff + ks * 32);
            #pragma unroll
            for (int np = 0; np < 8; np++) {
                uint32_t vH[4], vL[4];
                uint32_t va = (uint32_t)(ks * 16) * (XS * 2) + vrow0 + vcol + np * 32;
                LDSM4T(vH, sKhi + va);
                LDSM4T(vL, sKlo + va);
                mma16816(o[np * 2], pH, vH[0], vH[1]);
                mma16816(o[np * 2], pH, vL[0], vL[1]);
                mma16816(o[np * 2], pL, vH[0], vH[1]);
                mma16816(o[np * 2 + 1], pH, vH[2], vH[3]);
                mma16816(o[np * 2 + 1], pH, vL[2], vL[3]);
                mma16816(o[np * 2 + 1], pL, vH[2], vH[3]);
            }
        }
        cp_wait0();            // next K tile landed
        __syncthreads();       // PV done with kb + P; safe to overwrite
    }

    // ---- rowsum reduce: quads, then the 2 col-groups via smem ----
    rs0 += __shfl_xor_sync(0xffffffffu, rs0, 1);
    rs0 += __shfl_xor_sync(0xffffffffu, rs0, 2);
    rs1 += __shfl_xor_sync(0xffffffffu, rs1, 1);
    rs1 += __shfl_xor_sync(0xffffffffu, rs1, 2);
    float* rsm = (float*)(smem + SM_RS);       // [2][64]
    if (quad == 0) {
        rsm[cg * 64 + rg * 16 + (lane >> 2)] = rs0;
        rsm[cg * 64 + rg * 16 + (lane >> 2) + 8] = rs1;
    }
    __syncthreads();

    const int orow0 = rg * 16 + (lane >> 2);
    float inv0 = 1.f / (rsm[orow0] + rsm[64 + orow0]);
    float inv1 = 1.f / (rsm[orow0 + 8] + rsm[64 + orow0 + 8]);
    __syncthreads();

    // ---- A_det fp32 -> smem [64][260] (reuses Q region) ----
    float* Ad = (float*)smem;
    #pragma unroll
    for (int nt = 0; nt < 16; nt++) {
        int col = cg * 128 + nt * 8 + 2 * quad;
        Ad[orow0 * 260 + col] = o[nt][0] * inv0;
        Ad[orow0 * 260 + col + 1] = o[nt][1] * inv0;
        Ad[(orow0 + 8) * 260 + col] = o[nt][2] * inv1;
        Ad[(orow0 + 8) * 260 + col + 1] = o[nt][3] * inv1;
    }
    __syncthreads();

    // ---- SIMT projections + reparam epilogue ----
    const int ty = t >> 4, tx = t & 15;
    float am[4][4], al[4][4];
    #pragma unroll
    for (int i = 0; i < 4; i++)
        #pragma unroll
        for (int j = 0; j < 4; j++) { am[i][j] = 0.f; al[i][j] = 0.f; }

    const float4* wm4 = (const float4*)Wm;
    const float4* wl4 = (const float4*)Wl;
    #pragma unroll 4
    for (int k = 0; k < DD; k++) {
        float4 m4 = wm4[k * 16 + tx];
        float4 l4 = wl4[k * 16 + tx];
        #pragma unroll
        for (int i = 0; i < 4; i++) {
            float a = Ad[(ty * 4 + i) * 260 + k];
            am[i][0] += a * m4.x; am[i][1] += a * m4.y; am[i][2] += a * m4.z; am[i][3] += a * m4.w;
            al[i][0] += a * l4.x; al[i][1] += a * l4.y; al[i][2] += a * l4.z; al[i][3] += a * l4.w;
        }
    }

    const size_t BSA = (size_t)BB * SS * ADIM;
    float4 bm4 = ((const float4*)bmb)[tx];
    float4 bl4 = ((const float4*)blb)[tx];
    #pragma unroll
    for (int i = 0; i < 4; i++) {
        int row = qt * BM + ty * 4 + i;
        size_t base = (((size_t)b * SS + row) * ADIM) + tx * 4;
        float4 e4 = *((const float4*)(eps + base));
        float4 mo, lo, ao;
        mo.x = am[i][0] + bm4.x; mo.y = am[i][1] + bm4.y; mo.z = am[i][2] + bm4.z; mo.w = am[i][3] + bm4.w;
        lo.x = al[i][0] + bl4.x; lo.y = al[i][1] + bl4.y; lo.z = al[i][2] + bl4.z; lo.w = al[i][3] + bl4.w;
        ao.x = mo.x + __expf(0.5f * lo.x) * e4.x;
        ao.y = mo.y + __expf(0.5f * lo.y) * e4.y;
        ao.z = mo.z + __expf(0.5f * lo.z) * e4.z;
        ao.w = mo.w + __expf(0.5f * lo.w) * e4.w;
        *((float4*)(out + base)) = mo;
        *((float4*)(out + BSA + base)) = lo;
        *((float4*)(out + 2 * BSA + base)) = ao;
    }
}

extern "C" void kernel_launch(void* const* d_in, const int* in_sizes, int n_in,
                              void* d_out, int out_size)
{
    const float* x   = (const float*)d_in[0];
    const float* Wm  = (const float*)d_in[1];
    const float* bmb = (const float*)d_in[2];
    const float* Wl  = (const float*)d_in[3];
    const float* blb = (const float*)d_in[4];
    const float* eps = (const float*)d_in[5];

    vs_conv_kernel<<<BB * SS * DD / 4 / 256, 256>>>(x);

    cudaFuncSetAttribute(vs_mma_kernel, cudaFuncAttributeMaxDynamicSharedMemorySize, SMEM_BYTES);
    dim3 grid(SS / BM, BB);
    vs_mma_kernel<<<grid, THREADS, SMEM_BYTES>>>(Wm, bmb, Wl, blb, eps, (float*)d_out);
}

// round 13
// speedup vs baseline: 6.0918x; 1.0323x over previous
#include <cuda_runtime.h>
#include <cuda_bf16.h>
#include <cstdint>

#define BB 8
#define SS 2048
#define DD 256
#define ADIM 64
#define BM 64
#define BN 64
#define NT 32          // SS/BN
#define THREADS 512

#define XS2 528        // Q/K smem row stride bytes (264 bf16)
#define PS2 144        // P smem row stride bytes (72 bf16)

// smem byte offsets
#define SM_QHI 0
#define SM_QLO 33792
#define SM_K0  67584            // hi +0, lo +33792 (per 64-row tile)
#define SM_K1  135168
#define SM_PHI 202752
#define SM_PLO 211968
#define SM_RS  221184           // [4][64] fp32
#define SMEM_BYTES 222208

// pre-split x in bf16 (persistent device scratch; static allocation)
__device__ __nv_bfloat16 g_xhi[BB * SS * DD];
__device__ __nv_bfloat16 g_xlo[BB * SS * DD];

#define LDSM4(r, a) \
    asm volatile("ldmatrix.sync.aligned.m8n8.x4.shared.b16 {%0,%1,%2,%3}, [%4];" \
                 : "=r"((r)[0]), "=r"((r)[1]), "=r"((r)[2]), "=r"((r)[3]) : "r"(a))
#define LDSM4T(r, a) \
    asm volatile("ldmatrix.sync.aligned.m8n8.x4.trans.shared.b16 {%0,%1,%2,%3}, [%4];" \
                 : "=r"((r)[0]), "=r"((r)[1]), "=r"((r)[2]), "=r"((r)[3]) : "r"(a))

__device__ __forceinline__ void mma16816(float* c, const uint32_t* a, uint32_t b0, uint32_t b1) {
    asm volatile("mma.sync.aligned.m16n8k16.row.col.f32.bf16.bf16.f32 "
                 "{%0,%1,%2,%3}, {%4,%5,%6,%7}, {%8,%9}, {%0,%1,%2,%3};"
                 : "+f"(c[0]), "+f"(c[1]), "+f"(c[2]), "+f"(c[3])
                 : "r"(a[0]), "r"(a[1]), "r"(a[2]), "r"(a[3]), "r"(b0), "r"(b1));
}

__device__ __forceinline__ uint32_t smem_u32(const void* p) {
    uint32_t a;
    asm("{ .reg .u64 t; cvta.to.shared.u64 t, %1; cvt.u32.u64 %0, t; }" : "=r"(a) : "l"(p));
    return a;
}
__device__ __forceinline__ void cp_async16(uint32_t saddr, const void* gptr) {
    asm volatile("cp.async.cg.shared.global [%0], [%1], 16;\n" :: "r"(saddr), "l"(gptr));
}
__device__ __forceinline__ void cp_commit() { asm volatile("cp.async.commit_group;\n" ::: "memory"); }
__device__ __forceinline__ void cp_wait0()  { asm volatile("cp.async.wait_group 0;\n" ::: "memory"); }

__device__ __forceinline__ void split2(float a, float b, uint32_t& hi, uint32_t& lo) {
    __nv_bfloat162 h = __floats2bfloat162_rn(a, b);
    __nv_bfloat162 l = __floats2bfloat162_rn(a - __bfloat162float(h.x), b - __bfloat162float(h.y));
    hi = *reinterpret_cast<uint32_t*>(&h);
    lo = *reinterpret_cast<uint32_t*>(&l);
}

// ---------------- kernel A: x fp32 -> bf16 hi/lo split ----------------
__global__ __launch_bounds__(256, 4)
void vs_conv_kernel(const float* __restrict__ x)
{
    int i = blockIdx.x * 256 + threadIdx.x;
    float4 v = ((const float4*)x)[i];
    uint32_t h0, l0, h1, l1;
    split2(v.x, v.y, h0, l0);
    split2(v.z, v.w, h1, l1);
    uint2 h; h.x = h0; h.y = h1;
    uint2 l; l.x = l0; l.y = l1;
    ((uint2*)g_xhi)[i] = h;
    ((uint2*)g_xlo)[i] = l;
}

// ---------------- kernel B: attention + projections ----------------
__global__ __launch_bounds__(THREADS, 1)
void vs_mma_kernel(const float* __restrict__ Wm, const float* __restrict__ bmb,
                   const float* __restrict__ Wl, const float* __restrict__ blb,
                   const float* __restrict__ eps, float* __restrict__ out)
{
    extern __shared__ __align__(128) char smem[];
    const int b = blockIdx.y, qt = blockIdx.x, t = threadIdx.x;
    const int w = t >> 5, lane = t & 31;
    const int rg = w & 3;          // row group (16 rows)
    const int cg = w >> 2;         // 0..3: col group (S, 16 cols) / feat quarter (PV, 64)
    const int quad = lane & 3;

    const char* gxh = (const char*)g_xhi + (size_t)b * SS * DD * 2;
    const char* gxl = (const char*)g_xlo + (size_t)b * SS * DD * 2;

    // prologue: async-load Q tile + K tile 0 (each 64 rows, hi+lo)
    {
        const char* qh = gxh + (size_t)qt * BM * DD * 2;
        const char* ql = gxl + (size_t)qt * BM * DD * 2;
        #pragma unroll
        for (int k = 0; k < 4; k++) {
            int i = t + k * THREADS;            // 2048 chunks of 16B
            int r = i >> 5, c = i & 31;
            cp_async16(smem_u32(smem + SM_QHI + r * XS2 + c * 16), qh + r * 512 + c * 16);
            cp_async16(smem_u32(smem + SM_QLO + r * XS2 + c * 16), ql + r * 512 + c * 16);
            cp_async16(smem_u32(smem + SM_K0 + r * XS2 + c * 16), gxh + r * 512 + c * 16);
            cp_async16(smem_u32(smem + SM_K0 + 33792 + r * XS2 + c * 16), gxl + r * 512 + c * 16);
        }
        cp_commit();
        cp_wait0();
    }
    __syncthreads();

    const uint32_t sQhi = smem_u32(smem + SM_QHI), sQlo = smem_u32(smem + SM_QLO);
    const uint32_t sPhi = smem_u32(smem + SM_PHI), sPlo = smem_u32(smem + SM_PLO);

    // ldmatrix per-lane address offsets
    const int lrow = ((lane >> 3) & 1) * 8 + (lane & 7);
    const int lcol = (lane >> 4) * 16;
    const uint32_t aoff = (uint32_t)(rg * 16 + lrow) * XS2 + lcol;     // Q rows
    const uint32_t boff = (uint32_t)(cg * 16 + lrow) * XS2 + lcol;     // K rows (S phase)
    const uint32_t paoff = (uint32_t)(rg * 16 + lrow) * PS2 + lcol;    // P rows
    const uint32_t vcol = (uint32_t)(cg * 128 + (lane >> 4) * 16);     // PV feat quarter
    const uint32_t vrow0 = (uint32_t)lrow * XS2;

    float o[8][4];
    #pragma unroll
    for (int i = 0; i < 8; i++)
        #pragma unroll
        for (int j = 0; j < 4; j++) o[i][j] = 0.f;
    float rs0 = 0.f, rs1 = 0.f;

    for (int kt = 0; kt < NT; kt++) {
        const uint32_t kb = (kt & 1) ? SM_K1 : SM_K0;
        if (kt + 1 < NT) {
            const uint32_t nb = (kt & 1) ? SM_K0 : SM_K1;
            const char* kh = gxh + (size_t)(kt + 1) * BN * DD * 2;
            const char* kl = gxl + (size_t)(kt + 1) * BN * DD * 2;
            #pragma unroll
            for (int k = 0; k < 4; k++) {
                int i = t + k * THREADS;
                int r = i >> 5, c = i & 31;
                cp_async16(smem_u32(smem + nb + r * XS2 + c * 16), kh + r * 512 + c * 16);
                cp_async16(smem_u32(smem + nb + 33792 + r * XS2 + c * 16), kl + r * 512 + c * 16);
            }
            cp_commit();
        }
        const uint32_t sKhi = smem_u32(smem + kb), sKlo = smem_u32(smem + kb + 33792);

        // ---- S = Q K^T (16 rows x 16 cols per warp), bf16x3 ----
        float sc[2][4] = {{0.f, 0.f, 0.f, 0.f}, {0.f, 0.f, 0.f, 0.f}};
        #pragma unroll
        for (int ks = 0; ks < 16; ks++) {
            uint32_t aH[4], aL[4], bH[4], bL[4];
            LDSM4(aH, sQhi + aoff + ks * 32);
            LDSM4(aL, sQlo + aoff + ks * 32);
            LDSM4(bH, sKhi + boff + ks * 32);
            LDSM4(bL, sKlo + boff + ks * 32);
            mma16816(sc[0], aH, bH[0], bH[2]);
            mma16816(sc[0], aH, bL[0], bL[2]);
            mma16816(sc[0], aL, bH[0], bH[2]);
            mma16816(sc[1], aH, bH[1], bH[3]);
            mma16816(sc[1], aH, bL[1], bL[3]);
            mma16816(sc[1], aL, bH[1], bH[3]);
        }

        // ---- softmax numerators, rowsum partials, stage P hi/lo ----
        const int prow0 = rg * 16 + (lane >> 2);
        #pragma unroll
        for (int nt = 0; nt < 2; nt++) {
            float p0 = __expf(sc[nt][0] * 0.0625f);
            float p1 = __expf(sc[nt][1] * 0.0625f);
            float p2 = __expf(sc[nt][2] * 0.0625f);
            float p3 = __expf(sc[nt][3] * 0.0625f);
            rs0 += p0 + p1;  rs1 += p2 + p3;
            uint32_t h0, l0, h1, l1;
            split2(p0, p1, h0, l0);
            split2(p2, p3, h1, l1);
            uint32_t cb = (uint32_t)(cg * 16 + nt * 8 + 2 * quad) * 2;
            *(uint32_t*)(smem + SM_PHI + prow0 * PS2 + cb) = h0;
            *(uint32_t*)(smem + SM_PLO + prow0 * PS2 + cb) = l0;
            *(uint32_t*)(smem + SM_PHI + (prow0 + 8) * PS2 + cb) = h1;
            *(uint32_t*)(smem + SM_PLO + (prow0 + 8) * PS2 + cb) = l1;
        }
        __syncthreads();

        // ---- O += P V : warp = 16 rows x 64 feats (cg quarter), bf16x3 ----
        #pragma unroll
        for (int ks = 0; ks < 4; ks++) {
            uint32_t pH[4], pL[4];
            LDSM4(pH, sPhi + paoff + ks * 32);
            LDSM4(pL, sPlo + paoff + ks * 32);
            #pragma unroll
            for (int np = 0; np < 4; np++) {
                uint32_t vH[4], vL[4];
                uint32_t va = (uint32_t)(ks * 16) * XS2 + vrow0 + vcol + np * 32;
                LDSM4T(vH, sKhi + va);
                LDSM4T(vL, sKlo + va);
                mma16816(o[np * 2], pH, vH[0], vH[1]);
                mma16816(o[np * 2], pH, vL[0], vL[1]);
                mma16816(o[np * 2], pL, vH[0], vH[1]);
                mma16816(o[np * 2 + 1], pH, vH[2], vH[3]);
                mma16816(o[np * 2 + 1], pH, vL[2], vL[3]);
                mma16816(o[np * 2 + 1], pL, vH[2], vH[3]);
            }
        }
        cp_wait0();            // next K tile landed
        __syncthreads();       // PV done with kb + P; safe to overwrite
    }

    // ---- rowsum reduce: quads, then the 4 col-groups via smem ----
    rs0 += __shfl_xor_sync(0xffffffffu, rs0, 1);
    rs0 += __shfl_xor_sync(0xffffffffu, rs0, 2);
    rs1 += __shfl_xor_sync(0xffffffffu, rs1, 1);
    rs1 += __shfl_xor_sync(0xffffffffu, rs1, 2);
    float* rsm = (float*)(smem + SM_RS);       // [4][64]
    if (quad == 0) {
        rsm[cg * 64 + rg * 16 + (lane >> 2)] = rs0;
        rsm[cg * 64 + rg * 16 + (lane >> 2) + 8] = rs1;
    }
    __syncthreads();

    const int orow0 = rg * 16 + (lane >> 2);
    float inv0 = 1.f / (rsm[orow0] + rsm[64 + orow0] + rsm[128 + orow0] + rsm[192 + orow0]);
    float inv1 = 1.f / (rsm[orow0 + 8] + rsm[64 + orow0 + 8] + rsm[128 + orow0 + 8] + rsm[192 + orow0 + 8]);
    __syncthreads();

    // ---- A_det fp32 -> smem [64][260] (reuses Q region) ----
    float* Ad = (float*)smem;
    #pragma unroll
    for (int nt = 0; nt < 8; nt++) {
        int col = cg * 64 + nt * 8 + 2 * quad;
        Ad[orow0 * 260 + col] = o[nt][0] * inv0;
        Ad[orow0 * 260 + col + 1] = o[nt][1] * inv0;
        Ad[(orow0 + 8) * 260 + col] = o[nt][2] * inv1;
        Ad[(orow0 + 8) * 260 + col + 1] = o[nt][3] * inv1;
    }
    __syncthreads();

    // ---- SIMT projections + reparam epilogue: 512 thr, 2 rows x 4 cols each ----
    const int ty = t >> 4, tx = t & 15;        // ty 0..31
    float am[2][4], al[2][4];
    #pragma unroll
    for (int i = 0; i < 2; i++)
        #pragma unroll
        for (int j = 0; j < 4; j++) { am[i][j] = 0.f; al[i][j] = 0.f; }

    const float4* wm4 = (const float4*)Wm;
    const float4* wl4 = (const float4*)Wl;
    #pragma unroll 4
    for (int k = 0; k < DD; k++) {
        float4 m4 = wm4[k * 16 + tx];
        float4 l4 = wl4[k * 16 + tx];
        #pragma unroll
        for (int i = 0; i < 2; i++) {
            float a = Ad[(ty * 2 + i) * 260 + k];
            am[i][0] += a * m4.x; am[i][1] += a * m4.y; am[i][2] += a * m4.z; am[i][3] += a * m4.w;
            al[i][0] += a * l4.x; al[i][1] += a * l4.y; al[i][2] += a * l4.z; al[i][3] += a * l4.w;
        }
    }

    const size_t BSA = (size_t)BB * SS * ADIM;
    float4 bm4 = ((const float4*)bmb)[tx];
    float4 bl4 = ((const float4*)blb)[tx];
    #pragma unroll
    for (int i = 0; i < 2; i++) {
        int row = qt * BM + ty * 2 + i;
        size_t base = (((size_t)b * SS + row) * ADIM) + tx * 4;
        float4 e4 = *((const float4*)(eps + base));
        float4 mo, lo, ao;
        mo.x = am[i][0] + bm4.x; mo.y = am[i][1] + bm4.y; mo.z = am[i][2] + bm4.z; mo.w = am[i][3] + bm4.w;
        lo.x = al[i][0] + bl4.x; lo.y = al[i][1] + bl4.y; lo.z = al[i][2] + bl4.z; lo.w = al[i][3] + bl4.w;
        ao.x = mo.x + __expf(0.5f * lo.x) * e4.x;
        ao.y = mo.y + __expf(0.5f * lo.y) * e4.y;
        ao.z = mo.z + __expf(0.5f * lo.z) * e4.z;
        ao.w = mo.w + __expf(0.5f * lo.w) * e4.w;
        *((float4*)(out + base)) = mo;
        *((float4*)(out + BSA + base)) = lo;
        *((float4*)(out + 2 * BSA + base)) = ao;
    }
}

extern "C" void kernel_launch(void* const* d_in, const int* in_sizes, int n_in,
                              void* d_out, int out_size)
{
    const float* x   = (const float*)d_in[0];
    const float* Wm  = (const float*)d_in[1];
    const float* bmb = (const float*)d_in[2];
    const float* Wl  = (const float*)d_in[3];
    const float* blb = (const float*)d_in[4];
    const float* eps = (const float*)d_in[5];

    vs_conv_kernel<<<BB * SS * DD / 4 / 256, 256>>>(x);

    cudaFuncSetAttribute(vs_mma_kernel, cudaFuncAttributeMaxDynamicSharedMemorySize, SMEM_BYTES);
    dim3 grid(SS / BM, BB);
    vs_mma_kernel<<<grid, THREADS, SMEM_BYTES>>>(Wm, bmb, Wl, blb, eps, (float*)d_out);
}

// round 15
// speedup vs baseline: 6.1212x; 1.0048x over previous
#include <cuda_runtime.h>
#include <cuda_bf16.h>
#include <cstdint>

#define BB 8
#define SS 2048
#define DD 256
#define ADIM 64
#define BM 64
#define BN 128
#define NT 16          // SS/BN
#define THREADS 512

#define XS2 528        // Q/K smem row stride bytes
#define PS2 144        // P smem row stride bytes (64-key half)

// smem byte offsets
#define SM_QHI 0
#define SM_QLO 33792
#define SM_KHI 67584           // 128 rows x 528
#define SM_KLO 135168
#define SM_PHI 202752
#define SM_PLO 211968
#define SM_RS  221184
#define SMEM_BYTES 222208

__device__ __nv_bfloat16 g_xhi[BB * SS * DD];
__device__ __nv_bfloat16 g_xlo[BB * SS * DD];

#define LDSM4(r, a) \
    asm volatile("ldmatrix.sync.aligned.m8n8.x4.shared.b16 {%0,%1,%2,%3}, [%4];" \
                 : "=r"((r)[0]), "=r"((r)[1]), "=r"((r)[2]), "=r"((r)[3]) : "r"(a))
#define LDSM4T(r, a) \
    asm volatile("ldmatrix.sync.aligned.m8n8.x4.trans.shared.b16 {%0,%1,%2,%3}, [%4];" \
                 : "=r"((r)[0]), "=r"((r)[1]), "=r"((r)[2]), "=r"((r)[3]) : "r"(a))

__device__ __forceinline__ void mma16816(float* c, const uint32_t* a, uint32_t b0, uint32_t b1) {
    asm volatile("mma.sync.aligned.m16n8k16.row.col.f32.bf16.bf16.f32 "
                 "{%0,%1,%2,%3}, {%4,%5,%6,%7}, {%8,%9}, {%0,%1,%2,%3};"
                 : "+f"(c[0]), "+f"(c[1]), "+f"(c[2]), "+f"(c[3])
                 : "r"(a[0]), "r"(a[1]), "r"(a[2]), "r"(a[3]), "r"(b0), "r"(b1));
}

__device__ __forceinline__ uint32_t smem_u32(const void* p) {
    uint32_t a;
    asm("{ .reg .u64 t; cvta.to.shared.u64 t, %1; cvt.u32.u64 %0, t; }" : "=r"(a) : "l"(p));
    return a;
}
__device__ __forceinline__ void cp_async16(uint32_t saddr, const void* gptr) {
    asm volatile("cp.async.cg.shared.global [%0], [%1], 16;\n" :: "r"(saddr), "l"(gptr));
}
__device__ __forceinline__ void cp_commit() { asm volatile("cp.async.commit_group;\n" ::: "memory"); }
__device__ __forceinline__ void cp_wait0()  { asm volatile("cp.async.wait_group 0;\n" ::: "memory"); }

__device__ __forceinline__ void split2(float a, float b, uint32_t& hi, uint32_t& lo) {
    __nv_bfloat162 h = __floats2bfloat162_rn(a, b);
    __nv_bfloat162 l = __floats2bfloat162_rn(a - __bfloat162float(h.x), b - __bfloat162float(h.y));
    hi = *reinterpret_cast<uint32_t*>(&h);
    lo = *reinterpret_cast<uint32_t*>(&l);
}

// ---------------- kernel A: x fp32 -> bf16 hi/lo split ----------------
__global__ __launch_bounds__(256, 4)
void vs_conv_kernel(const float* __restrict__ x)
{
    int i = blockIdx.x * 256 + threadIdx.x;
    float4 v = ((const float4*)x)[i];
    uint32_t h0, l0, h1, l1;
    split2(v.x, v.y, h0, l0);
    split2(v.z, v.w, h1, l1);
    uint2 h; h.x = h0; h.y = h1;
    uint2 l; l.x = l0; l.y = l1;
    ((uint2*)g_xhi)[i] = h;
    ((uint2*)g_xlo)[i] = l;
}

// ---------------- kernel B: attention + projections ----------------
__global__ __launch_bounds__(THREADS, 1)
void vs_mma_kernel(const float* __restrict__ Wm, const float* __restrict__ bmb,
                   const float* __restrict__ Wl, const float* __restrict__ blb,
                   const float* __restrict__ eps, float* __restrict__ out)
{
    extern __shared__ __align__(128) char smem[];
    const int b = blockIdx.y, qt = blockIdx.x, t = threadIdx.x;
    const int w = t >> 5, lane = t & 31;
    const int rg = w & 3;          // 16-row group
    const int cg = w >> 2;         // S: 32-col group / PV: 64-feat quarter
    const int quad = lane & 3;

    const char* gxh = (const char*)g_xhi + (size_t)b * SS * DD * 2;
    const char* gxl = (const char*)g_xlo + (size_t)b * SS * DD * 2;

    // prologue: issue Q tile loads (hi+lo)
    {
        const char* qh = gxh + (size_t)qt * BM * DD * 2;
        const char* ql = gxl + (size_t)qt * BM * DD * 2;
        #pragma unroll
        for (int k = 0; k < 4; k++) {
            int i = t + k * THREADS;            // 2048 chunks per precision
            int r = i >> 5, c = i & 31;
            cp_async16(smem_u32(smem + SM_QHI + r * XS2 + c * 16), qh + r * 512 + c * 16);
            cp_async16(smem_u32(smem + SM_QLO + r * XS2 + c * 16), ql + r * 512 + c * 16);
        }
        cp_commit();
    }

    const uint32_t sQhi = smem_u32(smem + SM_QHI), sQlo = smem_u32(smem + SM_QLO);
    const uint32_t sKhi = smem_u32(smem + SM_KHI), sKlo = smem_u32(smem + SM_KLO);
    const uint32_t sPhi = smem_u32(smem + SM_PHI), sPlo = smem_u32(smem + SM_PLO);

    const int lrow = ((lane >> 3) & 1) * 8 + (lane & 7);
    const int lcol = (lane >> 4) * 16;
    const uint32_t aoff  = (uint32_t)(rg * 16 + lrow) * XS2 + lcol;          // Q rows
    const uint32_t boff0 = (uint32_t)(cg * 32 + lrow) * XS2 + lcol;          // K keys lo 16
    const uint32_t boff1 = boff0 + 16 * XS2;                                 // K keys hi 16
    const uint32_t paoff = (uint32_t)(rg * 16 + lrow) * PS2 + lcol;          // P rows
    const uint32_t vcol  = (uint32_t)(cg * 128 + (lane >> 4) * 16);          // feat quarter
    const uint32_t vrow0 = (uint32_t)lrow * XS2;

    float o[8][4];
    #pragma unroll
    for (int i = 0; i < 8; i++)
        #pragma unroll
        for (int j = 0; j < 4; j++) o[i][j] = 0.f;
    float rs0 = 0.f, rs1 = 0.f;
    const int prow0 = rg * 16 + (lane >> 2);

    for (int kt = 0; kt < NT; kt++) {
        __syncthreads();                       // prev PV done with K/P buffers
        // load K tile kt (128 keys, hi+lo), single-buffered
        {
            const char* kh = gxh + (size_t)kt * BN * DD * 2;
            const char* kl = gxl + (size_t)kt * BN * DD * 2;
            #pragma unroll
            for (int k = 0; k < 8; k++) {
                int i = t + k * THREADS;        // 4096 chunks per precision
                int r = i >> 5, c = i & 31;
                cp_async16(smem_u32(smem + SM_KHI + r * XS2 + c * 16), kh + r * 512 + c * 16);
                cp_async16(smem_u32(smem + SM_KLO + r * XS2 + c * 16), kl + r * 512 + c * 16);
            }
            cp_commit();
            cp_wait0();
        }
        __syncthreads();

        // ---- S = Q K^T : warp tile 16 x 32 (cols cg*32..+32), bf16x3 ----
        float sc[4][4];
        #pragma unroll
        for (int i = 0; i < 4; i++)
            #pragma unroll
            for (int j = 0; j < 4; j++) sc[i][j] = 0.f;

        #pragma unroll
        for (int ks = 0; ks < 16; ks++) {
            uint32_t aH[4], aL[4], b0[4], b1[4];
            LDSM4(aH, sQhi + aoff + ks * 32);
            LDSM4(aL, sQlo + aoff + ks * 32);
            LDSM4(b0, sKhi + boff0 + ks * 32);
            LDSM4(b1, sKhi + boff1 + ks * 32);
            mma16816(sc[0], aH, b0[0], b0[2]);
            mma16816(sc[1], aH, b0[1], b0[3]);
            mma16816(sc[2], aH, b1[0], b1[2]);
            mma16816(sc[3], aH, b1[1], b1[3]);
            mma16816(sc[0], aL, b0[0], b0[2]);
            mma16816(sc[1], aL, b0[1], b0[3]);
            mma16816(sc[2], aL, b1[0], b1[2]);
            mma16816(sc[3], aL, b1[1], b1[3]);
            LDSM4(b0, sKlo + boff0 + ks * 32);
            LDSM4(b1, sKlo + boff1 + ks * 32);
            mma16816(sc[0], aH, b0[0], b0[2]);
            mma16816(sc[1], aH, b0[1], b0[3]);
            mma16816(sc[2], aH, b1[0], b1[2]);
            mma16816(sc[3], aH, b1[1], b1[3]);
        }

        // ---- exp, rowsum partials, split P (kept in regs until store) ----
        uint32_t ph[4], pl[4], ph2[4], pl2[4];
        #pragma unroll
        for (int nt = 0; nt < 4; nt++) {
            float p0 = __expf(sc[nt][0] * 0.0625f);
            float p1 = __expf(sc[nt][1] * 0.0625f);
            float p2 = __expf(sc[nt][2] * 0.0625f);
            float p3 = __expf(sc[nt][3] * 0.0625f);
            rs0 += p0 + p1;  rs1 += p2 + p3;
            split2(p0, p1, ph[nt], pl[nt]);
            split2(p2, p3, ph2[nt], pl2[nt]);
        }

        const uint32_t cb0 = (uint32_t)((cg & 1) * 32);
        // store P for key-half 0 (warps cg<2 own keys 0..63)
        if (cg < 2) {
            #pragma unroll
            for (int nt = 0; nt < 4; nt++) {
                uint32_t cb = (cb0 + nt * 8 + 2 * quad) * 2;
                *(uint32_t*)(smem + SM_PHI + prow0 * PS2 + cb) = ph[nt];
                *(uint32_t*)(smem + SM_PLO + prow0 * PS2 + cb) = pl[nt];
                *(uint32_t*)(smem + SM_PHI + (prow0 + 8) * PS2 + cb) = ph2[nt];
                *(uint32_t*)(smem + SM_PLO + (prow0 + 8) * PS2 + cb) = pl2[nt];
            }
        }
        __syncthreads();

        // ---- PV half 0: O += P(keys 0..63) V(keys 0..63, feat quarter) ----
        #pragma unroll
        for (int ks = 0; ks < 4; ks++) {
            uint32_t pH[4], pL[4];
            LDSM4(pH, sPhi + paoff + ks * 32);
            LDSM4(pL, sPlo + paoff + ks * 32);
            #pragma unroll
            for (int np = 0; np < 4; np++) {
                uint32_t vH[4], vL[4];
                uint32_t va = (uint32_t)(ks * 16) * XS2 + vrow0 + vcol + np * 32;
                LDSM4T(vH, sKhi + va);
                LDSM4T(vL, sKlo + va);
                mma16816(o[np * 2], pH, vH[0], vH[1]);
                mma16816(o[np * 2], pH, vL[0], vL[1]);
                mma16816(o[np * 2], pL, vH[0], vH[1]);
                mma16816(o[np * 2 + 1], pH, vH[2], vH[3]);
                mma16816(o[np * 2 + 1], pH, vL[2], vL[3]);
                mma16816(o[np * 2 + 1], pL, vH[2], vH[3]);
            }
        }
        __syncthreads();

        // store P for key-half 1 (warps cg>=2 own keys 64..127)
        if (cg >= 2) {
            #pragma unroll
            for (int nt = 0; nt < 4; nt++) {
                uint32_t cb = (cb0 + nt * 8 + 2 * quad) * 2;
                *(uint32_t*)(smem + SM_PHI + prow0 * PS2 + cb) = ph[nt];
                *(uint32_t*)(smem + SM_PLO + prow0 * PS2 + cb) = pl[nt];
                *(uint32_t*)(smem + SM_PHI + (prow0 + 8) * PS2 + cb) = ph2[nt];
                *(uint32_t*)(smem + SM_PLO + (prow0 + 8) * PS2 + cb) = pl2[nt];
            }
        }
        __syncthreads();

        // ---- PV half 1: keys 64..127 ----
        #pragma unroll
        for (int ks = 0; ks < 4; ks++) {
            uint32_t pH[4], pL[4];
            LDSM4(pH, sPhi + paoff + ks * 32);
            LDSM4(pL, sPlo + paoff + ks * 32);
            #pragma unroll
            for (int np = 0; np < 4; np++) {
                uint32_t vH[4], vL[4];
                uint32_t va = (uint32_t)(64 + ks * 16) * XS2 + vrow0 + vcol + np * 32;
                LDSM4T(vH, sKhi + va);
                LDSM4T(vL, sKlo + va);
                mma16816(o[np * 2], pH, vH[0], vH[1]);
                mma16816(o[np * 2], pH, vL[0], vL[1]);
                mma16816(o[np * 2], pL, vH[0], vH[1]);
                mma16816(o[np * 2 + 1], pH, vH[2], vH[3]);
                mma16816(o[np * 2 + 1], pH, vL[2], vL[3]);
                mma16816(o[np * 2 + 1], pL, vH[2], vH[3]);
            }
        }
    }

    // ---- rowsum reduce: quads, then 4 col-groups via smem ----
    rs0 += __shfl_xor_sync(0xffffffffu, rs0, 1);
    rs0 += __shfl_xor_sync(0xffffffffu, rs0, 2);
    rs1 += __shfl_xor_sync(0xffffffffu, rs1, 1);
    rs1 += __shfl_xor_sync(0xffffffffu, rs1, 2);
    float* rsm = (float*)(smem + SM_RS);       // [4][64]
    if (quad == 0) {
        rsm[cg * 64 + rg * 16 + (lane >> 2)] = rs0;
        rsm[cg * 64 + rg * 16 + (lane >> 2) + 8] = rs1;
    }
    __syncthreads();

    const int orow0 = rg * 16 + (lane >> 2);
    float inv0 = 1.f / (rsm[orow0] + rsm[64 + orow0] + rsm[128 + orow0] + rsm[192 + orow0]);
    float inv1 = 1.f / (rsm[orow0 + 8] + rsm[64 + orow0 + 8] + rsm[128 + orow0 + 8] + rsm[192 + orow0 + 8]);
    __syncthreads();

    // ---- A_det fp32 -> smem [64][260] (reuses Q region) ----
    float* Ad = (float*)smem;
    #pragma unroll
    for (int nt = 0; nt < 8; nt++) {
        int col = cg * 64 + nt * 8 + 2 * quad;
        Ad[orow0 * 260 + col] = o[nt][0] * inv0;
        Ad[orow0 * 260 + col + 1] = o[nt][1] * inv0;
        Ad[(orow0 + 8) * 260 + col] = o[nt][2] * inv1;
        Ad[(orow0 + 8) * 260 + col + 1] = o[nt][3] * inv1;
    }
    __syncthreads();

    // ---- SIMT projections + reparam epilogue: 2 rows x 4 cols/thread ----
    const int ty = t >> 4, tx = t & 15;
    float am[2][4], al[2][4];
    #pragma unroll
    for (int i = 0; i < 2; i++)
        #pragma unroll
        for (int j = 0; j < 4; j++) { am[i][j] = 0.f; al[i][j] = 0.f; }

    const float4* wm4 = (const float4*)Wm;
    const float4* wl4 = (const float4*)Wl;
    #pragma unroll 4
    for (int k = 0; k < DD; k++) {
        float4 m4 = wm4[k * 16 + tx];
        float4 l4 = wl4[k * 16 + tx];
        #pragma unroll
        for (int i = 0; i < 2; i++) {
            float a = Ad[(ty * 2 + i) * 260 + k];
            am[i][0] += a * m4.x; am[i][1] += a * m4.y; am[i][2] += a * m4.z; am[i][3] += a * m4.w;
            al[i][0] += a * l4.x; al[i][1] += a * l4.y; al[i][2] += a * l4.z; al[i][3] += a * l4.w;
        }
    }

    const size_t BSA = (size_t)BB * SS * ADIM;
    float4 bm4 = ((const float4*)bmb)[tx];
    float4 bl4 = ((const float4*)blb)[tx];
    #pragma unroll
    for (int i = 0; i < 2; i++) {
        int row = qt * BM + ty * 2 + i;
        size_t base = (((size_t)b * SS + row) * ADIM) + tx * 4;
        float4 e4 = *((const float4*)(eps + base));
        float4 mo, lo, ao;
        mo.x = am[i][0] + bm4.x; mo.y = am[i][1] + bm4.y; mo.z = am[i][2] + bm4.z; mo.w = am[i][3] + bm4.w;
        lo.x = al[i][0] + bl4.x; lo.y = al[i][1] + bl4.y; lo.z = al[i][2] + bl4.z; lo.w = al[i][3] + bl4.w;
        ao.x = mo.x + __expf(0.5f * lo.x) * e4.x;
        ao.y = mo.y + __expf(0.5f * lo.y) * e4.y;
        ao.z = mo.z + __expf(0.5f * lo.z) * e4.z;
        ao.w = mo.w + __expf(0.5f * lo.w) * e4.w;
        *((float4*)(out + base)) = mo;
        *((float4*)(out + BSA + base)) = lo;
        *((float4*)(out + 2 * BSA + base)) = ao;
    }
}

extern "C" void kernel_launch(void* const* d_in, const int* in_sizes, int n_in,
                              void* d_out, int out_size)
{
    const float* x   = (const float*)d_in[0];
    const float* Wm  = (const float*)d_in[1];
    const float* bmb = (const float*)d_in[2];
    const float* Wl  = (const float*)d_in[3];
    const float* blb = (const float*)d_in[4];
    const float* eps = (const float*)d_in[5];

    vs_conv_kernel<<<BB * SS * DD / 4 / 256, 256>>>(x);

    cudaFuncSetAttribute(vs_mma_kernel, cudaFuncAttributeMaxDynamicSharedMemorySize, SMEM_BYTES);
    dim3 grid(SS / BM, BB);
    vs_mma_kernel<<<grid, THREADS, SMEM_BYTES>>>(Wm, bmb, Wl, blb, eps, (float*)d_out);
}